// round 14
// baseline (speedup 1.0000x reference)
#include <cuda_runtime.h>
#include <cuda_bf16.h>
#include <stdint.h>
#include <math.h>

#define BB 4
#define MM 8192
#define LL 64
#define DM 1024
#define IND 512
#define NH 8
#define DH 64
#define S_TOT (MM + LL)            // 8256
#define ROWS_X (BB * MM)           // 32768
#define ROWS_KV (BB * S_TOT)       // 33024
#define ROWS_L (BB * LL)           // 256
#define NCHUNK 9                   // 9 chunks: 8 x 960 keys + 1 x 576 keys
#define CHUNK_KEYS 960

// ---------------- scratch ----------------
__device__ float g_ln[ROWS_L * DM];
__device__ __nv_bfloat16 g_Ahi[(size_t)ROWS_KV * DM];
__device__ __nv_bfloat16 g_Alo[(size_t)ROWS_KV * DM];
__device__ __nv_bfloat16 g_Whi[(size_t)DM * DM];    // transposed: [n][k]
__device__ __nv_bfloat16 g_Wlo[(size_t)DM * DM];
__device__ float g_kv[(size_t)ROWS_KV * 2 * IND];
__device__ float g_q[ROWS_L * IND];
__device__ float g_po[BB * NH * NCHUNK * LL * DH];
__device__ float g_pm[BB * NH * NCHUNK * LL];
__device__ float g_pl[BB * NH * NCHUNK * LL];
__device__ float g_ao[ROWS_L * IND];

__device__ __forceinline__ float warpSum(float v) {
#pragma unroll
    for (int o = 16; o; o >>= 1) v += __shfl_xor_sync(0xffffffffu, v, o);
    return v;
}
__device__ __forceinline__ float warpMax(float v) {
#pragma unroll
    for (int o = 16; o; o >>= 1) v = fmaxf(v, __shfl_xor_sync(0xffffffffu, v, o));
    return v;
}

// ---------------- PTX helpers ----------------
__device__ __forceinline__ uint32_t smem_u32(const void* p) {
    uint32_t a;
    asm("{ .reg .u64 t; cvta.to.shared.u64 t, %1; cvt.u32.u64 %0, t; }" : "=r"(a) : "l"(p));
    return a;
}
__device__ __forceinline__ uint32_t elect_one() {
    uint32_t pred;
    asm volatile("{\n\t.reg .pred p;\n\telect.sync _|p, 0xFFFFFFFF;\n\tselp.b32 %0, 1, 0, p;\n\t}" : "=r"(pred));
    return pred;
}
__device__ __forceinline__ void cp16(uint32_t dst, const void* src) {
    asm volatile("cp.async.cg.shared.global [%0], [%1], 16;" :: "r"(dst), "l"(src));
}
#define CP_COMMIT() asm volatile("cp.async.commit_group;" ::: "memory")
#define CP_WAIT(n)  asm volatile("cp.async.wait_group %0;" :: "n"(n) : "memory")
#define CP_MBAR_ARRIVE(addr) \
    asm volatile("cp.async.mbarrier.arrive.noinc.shared::cta.b64 [%0];" :: "r"(addr) : "memory")
#define MBAR_INIT(addr, cnt) \
    asm volatile("mbarrier.init.shared.b64 [%0], %1;" :: "r"(addr), "r"(cnt) : "memory")
#define MBAR_WAIT(addr, parity) do { \
    uint32_t _m = (addr); uint32_t _p = (parity); uint32_t _done; \
    asm volatile("{\n\t.reg .pred p;\n\tmbarrier.try_wait.parity.acquire.cta.shared::cta.b64 p, [%1], %2;\n\tselp.b32 %0, 1, 0, p;\n\t}" \
        : "=r"(_done) : "r"(_m), "r"(_p) : "memory"); \
    if (!_done) { \
        asm volatile("{\n\t.reg .pred P1;\n\tWL_%=:\n\tmbarrier.try_wait.parity.acquire.cta.shared::cta.b64 P1, [%0], %1, 0x989680;\n\t@P1 bra.uni WD_%=;\n\tbra.uni WL_%=;\n\tWD_%=:\n\t}" \
            :: "r"(_m), "r"(_p) : "memory"); \
    } } while (0)
#define FENCE_ASYNC() asm volatile("fence.proxy.async.shared::cta;" ::: "memory")

#if defined(__CUDA_ARCH_FEAT_SM103_ALL) || defined(__CUDA_ARCH_FEAT_SM100_ALL)
#define HAS_TCGEN05 1
#else
#define HAS_TCGEN05 0
#endif

#if HAS_TCGEN05
#define TC_ALLOC(smem_addr, ncols) \
    asm volatile("tcgen05.alloc.cta_group::1.sync.aligned.shared::cta.b32 [%0], %1;" :: "r"(smem_addr), "r"(ncols) : "memory")
#define TC_DEALLOC(tmem, ncols) \
    asm volatile("tcgen05.dealloc.cta_group::1.sync.aligned.b32 %0, %1;" :: "r"(tmem), "r"(ncols))
#define TC_RELINQ() \
    asm volatile("tcgen05.relinquish_alloc_permit.cta_group::1.sync.aligned;")
#define TC_COMMIT(mbar) \
    asm volatile("tcgen05.commit.cta_group::1.mbarrier::arrive::one.shared::cluster.b64 [%0];" :: "r"(mbar) : "memory")
#define TC_FENCE_AFTER() asm volatile("tcgen05.fence::after_thread_sync;" ::: "memory")
#define TC_WAIT_LD() asm volatile("tcgen05.wait::ld.sync.aligned;" ::: "memory")

__device__ __forceinline__ void mma_f16_ss(uint32_t d, uint64_t ad, uint64_t bd,
                                           uint32_t idesc, uint32_t en) {
    asm volatile(
        "{\n\t.reg .pred p;\n\tsetp.ne.u32 p, %4, 0;\n\t"
        "tcgen05.mma.cta_group::1.kind::f16 [%0], %1, %2, %3, {%5, %5, %5, %5}, p;\n\t}"
        :: "r"(d), "l"(ad), "l"(bd), "r"(idesc), "r"(en), "r"(0u) : "memory");
}
#define LDTM_X32(r, addr) \
    asm volatile("tcgen05.ld.sync.aligned.32x32b.x32.b32 " \
        "{%0,%1,%2,%3,%4,%5,%6,%7,%8,%9,%10,%11,%12,%13,%14,%15," \
        "%16,%17,%18,%19,%20,%21,%22,%23,%24,%25,%26,%27,%28,%29,%30,%31}, [%32];" \
        : "=r"((r)[0]),"=r"((r)[1]),"=r"((r)[2]),"=r"((r)[3]),"=r"((r)[4]),"=r"((r)[5]),"=r"((r)[6]),"=r"((r)[7]), \
          "=r"((r)[8]),"=r"((r)[9]),"=r"((r)[10]),"=r"((r)[11]),"=r"((r)[12]),"=r"((r)[13]),"=r"((r)[14]),"=r"((r)[15]), \
          "=r"((r)[16]),"=r"((r)[17]),"=r"((r)[18]),"=r"((r)[19]),"=r"((r)[20]),"=r"((r)[21]),"=r"((r)[22]),"=r"((r)[23]), \
          "=r"((r)[24]),"=r"((r)[25]),"=r"((r)[26]),"=r"((r)[27]),"=r"((r)[28]),"=r"((r)[29]),"=r"((r)[30]),"=r"((r)[31]) \
        : "r"(addr))
#endif

// SW64 K-major desc: layout=4, version=1, SBO=32 (512B atom stride), LBO=1
__device__ __forceinline__ uint64_t make_desc64(uint32_t saddr) {
    const uint64_t base = (uint64_t(4) << 61) | (uint64_t(1) << 46) | (uint64_t(32) << 32) | (uint64_t(1) << 16);
    return base | ((uint64_t)(saddr >> 4) & 0x3FFF);
}
// idesc: F32 accum, BF16 a/b, N=256, M=128
#define KV_IDESC ((1u << 4) | (1u << 7) | (1u << 10) | (32u << 17) | (8u << 24))

// ---------------- 1. LN + bf16 hi/lo split, warp-per-row ----------------
__global__ void __launch_bounds__(256) prep_a_kernel(
    const float* __restrict__ x, const float* __restrict__ lat,
    const float* __restrict__ gm, const float* __restrict__ bm,
    const float* __restrict__ gl, const float* __restrict__ bl)
{
    int wid = threadIdx.x >> 5, lane = threadIdx.x & 31;
    int row = blockIdx.x * 8 + wid;
    bool isx = row < ROWS_X;
    const float4* src = reinterpret_cast<const float4*>(
        isx ? (x + (size_t)row * DM) : (lat + (size_t)(row - ROWS_X) * DM));

    float4 v[8];
    float s = 0.f, sq = 0.f;
#pragma unroll
    for (int i = 0; i < 8; i++) {
        v[i] = src[lane + 32 * i];
        s  += v[i].x + v[i].y + v[i].z + v[i].w;
        sq += v[i].x * v[i].x + v[i].y * v[i].y + v[i].z * v[i].z + v[i].w * v[i].w;
    }
    s = warpSum(s); sq = warpSum(sq);
    float mean = s * (1.0f / 1024.0f);
    float var  = sq * (1.0f / 1024.0f) - mean * mean;
    float rstd = rsqrtf(var + 1e-5f);

    const float4* gp = reinterpret_cast<const float4*>(isx ? gm : gl);
    const float4* bp = reinterpret_cast<const float4*>(isx ? bm : bl);

    int arow;
    float* lnrow = nullptr;
    if (isx) {
        int bb = row >> 13, ss = row & 8191;
        arow = bb * S_TOT + ss;
    } else {
        int lr = row - ROWS_X;
        int bb = lr >> 6, j = lr & 63;
        arow = bb * S_TOT + MM + j;
        lnrow = g_ln + (size_t)lr * DM;
    }
    uint2* hdst = reinterpret_cast<uint2*>(g_Ahi + (size_t)arow * DM);
    uint2* ldst = reinterpret_cast<uint2*>(g_Alo + (size_t)arow * DM);

#pragma unroll
    for (int i = 0; i < 8; i++) {
        float4 g4 = gp[lane + 32 * i];
        float4 b4 = bp[lane + 32 * i];
        float4 o;
        o.x = (v[i].x - mean) * rstd * g4.x + b4.x;
        o.y = (v[i].y - mean) * rstd * g4.y + b4.y;
        o.z = (v[i].z - mean) * rstd * g4.z + b4.z;
        o.w = (v[i].w - mean) * rstd * g4.w + b4.w;
        if (lnrow) reinterpret_cast<float4*>(lnrow)[lane + 32 * i] = o;

        __nv_bfloat16 hx = __float2bfloat16(o.x), hy = __float2bfloat16(o.y);
        __nv_bfloat16 hz = __float2bfloat16(o.z), hw = __float2bfloat16(o.w);
        float rx = o.x - __bfloat162float(hx), ry = o.y - __bfloat162float(hy);
        float rz = o.z - __bfloat162float(hz), rw = o.w - __bfloat162float(hw);
        __nv_bfloat162 h01 = __nv_bfloat162(hx, hy), h23 = __nv_bfloat162(hz, hw);
        __nv_bfloat162 l01 = __floats2bfloat162_rn(rx, ry), l23 = __floats2bfloat162_rn(rz, rw);
        uint2 uh, ul;
        uh.x = *reinterpret_cast<uint32_t*>(&h01); uh.y = *reinterpret_cast<uint32_t*>(&h23);
        ul.x = *reinterpret_cast<uint32_t*>(&l01); ul.y = *reinterpret_cast<uint32_t*>(&l23);
        hdst[lane + 32 * i] = uh;
        ldst[lane + 32 * i] = ul;
    }
}

// ---------------- 2. W transpose + hi/lo split ----------------
__global__ void __launch_bounds__(256) prep_w_kernel(const float* __restrict__ Wkv)
{
    __shared__ float s[64][33];
    int n0 = blockIdx.x * 32;
    int k0 = blockIdx.y * 64;
    int tid = threadIdx.x;

#pragma unroll
    for (int it = 0; it < 8; it++) {
        int idx = it * 256 + tid;
        int i = idx >> 5, j = idx & 31;
        s[i][j] = Wkv[(size_t)(k0 + i) * (2 * IND) + n0 + j];
    }
    __syncthreads();

#pragma unroll
    for (int it = 0; it < 4; it++) {
        int idx = it * 256 + tid;
        int j  = idx >> 5;
        int ii = (idx & 31) * 2;
        float v0 = s[ii][j], v1 = s[ii + 1][j];
        __nv_bfloat16 h0 = __float2bfloat16(v0), h1 = __float2bfloat16(v1);
        float r0 = v0 - __bfloat162float(h0), r1 = v1 - __bfloat162float(h1);
        __nv_bfloat162 hp = __nv_bfloat162(h0, h1);
        __nv_bfloat162 lp = __floats2bfloat162_rn(r0, r1);
        size_t off = ((size_t)(n0 + j) * DM + k0 + ii) >> 1;
        reinterpret_cast<uint32_t*>(g_Whi)[off] = *reinterpret_cast<uint32_t*>(&hp);
        reinterpret_cast<uint32_t*>(g_Wlo)[off] = *reinterpret_cast<uint32_t*>(&lp);
    }
}

// ---------------- 3. q = ln @ Wq (vectorized: 4 cols x 2 rows per thread) ----------------
// 16384 threads = 64 blocks x 256. thread: n4 = (o&127)*4, rg = o>>7 (rows rg, rg+128)
__global__ void __launch_bounds__(256) q_gemm_kernel(const float* __restrict__ Wq)
{
    int o = blockIdx.x * 256 + threadIdx.x;
    int n4 = (o & 127) * 4;
    int rg = o >> 7;                       // 0..127
    float4 a0 = make_float4(0.f, 0.f, 0.f, 0.f);
    float4 a1 = make_float4(0.f, 0.f, 0.f, 0.f);
    const float* l0 = g_ln + (size_t)rg * DM;
    const float* l1 = g_ln + (size_t)(rg + 128) * DM;
    const float4* Wv = reinterpret_cast<const float4*>(Wq) + (n4 >> 2);
    for (int k = 0; k < DM; k++) {
        float4 wv = __ldg(Wv + (size_t)k * (IND / 4));
        float x0 = l0[k], x1 = l1[k];
        a0.x += x0 * wv.x; a0.y += x0 * wv.y; a0.z += x0 * wv.z; a0.w += x0 * wv.w;
        a1.x += x1 * wv.x; a1.y += x1 * wv.y; a1.z += x1 * wv.z; a1.w += x1 * wv.w;
    }
    *reinterpret_cast<float4*>(g_q + (size_t)rg * IND + n4)         = a0;
    *reinterpret_cast<float4*>(g_q + (size_t)(rg + 128) * IND + n4) = a1;
}

// ---------------- 4. KV GEMM (unchanged — at LTS floor) ----------------
#define OFF_AHI 0
#define OFF_ALO 16384
#define OFF_WHI 32768
#define OFF_WLO 49152
#define STAGE_BYTES 65536
#define NSTAGE 3
#define SM_TM   0
#define SM_MB   64
#define SM_DATA 1024
#define SM_TOT  (SM_DATA + NSTAGE * STAGE_BYTES)

__global__ void __launch_bounds__(256) kv_gemm_tc()
{
#if HAS_TCGEN05
    extern __shared__ char smem[];
    uint32_t sb = smem_u32(smem);
    int tid = threadIdx.x, wid = tid >> 5;
    int ntile = blockIdx.x, mtile = blockIdx.y;

    if (wid == 0) { TC_ALLOC(sb + SM_TM, 512); TC_RELINQ(); }
    if (tid == 0) {
#pragma unroll
        for (int st = 0; st < NSTAGE; st++) {
            MBAR_INIT(sb + SM_MB + st * 16, 256);
            MBAR_INIT(sb + SM_MB + st * 16 + 8, 1);
        }
    }
    __syncthreads();
    uint32_t tmem;
    asm volatile("ld.shared.b32 %0, [%1];" : "=r"(tmem) : "r"(sb + SM_TM));

    const char* Ah = (const char*)g_Ahi + (size_t)(mtile * 256) * 2048;
    const char* Al = (const char*)g_Alo + (size_t)(mtile * 256) * 2048;
    const char* Wh = (const char*)g_Whi + (size_t)(ntile * 256) * 2048;
    const char* Wl = (const char*)g_Wlo + (size_t)(ntile * 256) * 2048;

    uint32_t c_src[4], c_dst[4];
#pragma unroll
    for (int it = 0; it < 4; it++) {
        int idx = it * 256 + tid;
        int row = idx >> 2, cb = idx & 3;
        c_src[it] = (uint32_t)(row * 2048 + cb * 16);
        uint32_t bo = (uint32_t)(row * 64 + cb * 16);
        c_dst[it] = bo ^ ((bo >> 3) & 0x30);
    }

#define FILL_STAGE(st, kc) do { \
        uint32_t sbase = sb + SM_DATA + (st) * STAGE_BYTES; \
        uint32_t koff = (uint32_t)(kc) * 64; \
        _Pragma("unroll") \
        for (int it = 0; it < 4; it++) { \
            cp16(sbase + OFF_AHI + c_dst[it], Ah + c_src[it] + koff); \
            cp16(sbase + OFF_ALO + c_dst[it], Al + c_src[it] + koff); \
            cp16(sbase + OFF_WHI + c_dst[it], Wh + c_src[it] + koff); \
            cp16(sbase + OFF_WLO + c_dst[it], Wl + c_src[it] + koff); \
        } \
        CP_MBAR_ARRIVE(sb + SM_MB + (st) * 16); \
    } while (0)

    FILL_STAGE(0, 0);
    FILL_STAGE(1, 1);
    FILL_STAGE(2, 2);

    int fc[NSTAGE] = {0, 0, 0};
    int ec[NSTAGE] = {0, 0, 0};

    for (int kc = 0; kc < 32; kc++) {
        int st = kc - (kc / 3) * 3;

        if (wid == 0 && elect_one()) {
            MBAR_WAIT(sb + SM_MB + st * 16, (uint32_t)(fc[st] & 1));
            fc[st]++;
            FENCE_ASYNC();
            uint32_t sbase = sb + SM_DATA + st * STAGE_BYTES;
            uint64_t ahd = make_desc64(sbase + OFF_AHI);
            uint64_t ald = make_desc64(sbase + OFF_ALO);
            uint64_t whd = make_desc64(sbase + OFF_WHI);
            uint64_t wld = make_desc64(sbase + OFF_WLO);
#pragma unroll
            for (int sub = 0; sub < 2; sub++) {
                uint32_t dtm = tmem + sub * 256;
                uint64_t aoff = (uint64_t)(sub * 512);
#pragma unroll
                for (int s = 0; s < 2; s++) {
                    uint32_t en = !(kc == 0 && s == 0);
                    mma_f16_ss(dtm, ahd + aoff + s * 2, whd + s * 2, KV_IDESC, en);
                }
#pragma unroll
                for (int s = 0; s < 2; s++)
                    mma_f16_ss(dtm, ahd + aoff + s * 2, wld + s * 2, KV_IDESC, 1);
#pragma unroll
                for (int s = 0; s < 2; s++)
                    mma_f16_ss(dtm, ald + aoff + s * 2, whd + s * 2, KV_IDESC, 1);
            }
            TC_COMMIT(sb + SM_MB + st * 16 + 8);
        }

        if (kc >= 1 && kc + 2 <= 31) {
            int stp = (kc + 2) - ((kc + 2) / 3) * 3;
            MBAR_WAIT(sb + SM_MB + stp * 16 + 8, (uint32_t)(ec[stp] & 1));
            ec[stp]++;
            FILL_STAGE(stp, kc + 2);
        }
    }

#pragma unroll
    for (int st = 0; st < NSTAGE; st++) {
        MBAR_WAIT(sb + SM_MB + st * 16 + 8, (uint32_t)(ec[st] & 1));
        ec[st]++;
    }
    TC_FENCE_AFTER();

    {
        int lane = tid & 31;
        int half = wid >> 2;
        int wiw  = wid & 3;
        uint32_t tbase = tmem + half * 256;
        size_t rowg = (size_t)(mtile * 256 + half * 128 + wiw * 32 + lane);
        float* dst = g_kv + rowg * (2 * IND) + ntile * 256;
#pragma unroll
        for (int cb = 0; cb < 8; cb++) {
            uint32_t r[32];
            LDTM_X32(r, tbase + cb * 32);
            TC_WAIT_LD();
#pragma unroll
            for (int j = 0; j < 32; j += 4) {
                uint4 v;
                v.x = r[j]; v.y = r[j + 1]; v.z = r[j + 2]; v.w = r[j + 3];
                *reinterpret_cast<uint4*>(dst + cb * 32 + j) = v;
            }
        }
    }
    __syncthreads();
    if (wid == 0) TC_DEALLOC(tmem, 512);
#undef FILL_STAGE
#else
    int tid = threadIdx.x;
    int ntile = blockIdx.x, mtile = blockIdx.y;
    for (int i = tid; i < 256 * 256; i += 256) {
        int r = i >> 8, cc = i & 255;
        size_t row = (size_t)mtile * 256 + r;
        size_t col = (size_t)ntile * 256 + cc;
        float acc = 0.f;
        for (int k = 0; k < DM; k++) {
            float a = __bfloat162float(g_Ahi[row * DM + k]) + __bfloat162float(g_Alo[row * DM + k]);
            float w = __bfloat162float(g_Whi[col * DM + k]) + __bfloat162float(g_Wlo[col * DM + k]);
            acc += a * w;
        }
        g_kv[row * (2 * IND) + col] = acc;
    }
#endif
}

// ---------------- 5. split-KV flash attention: 64-key tiles, 960-key chunks (1 wave) ----------------
#define AQ_QS 0
#define AQ_KS 4096
#define AQ_VS 12800
#define AQ_PS 20992
#define AQ_TOT_F 25344
#define KS_STRIDE 68
#define PS_STRIDE 68

__global__ void __launch_bounds__(512) attn_kernel()
{
    extern __shared__ float sm[];
    float* QS = sm + AQ_QS;
    float* KS = sm + AQ_KS;
    float* VS = sm + AQ_VS;
    float* PS = sm + AQ_PS;
    uint32_t ks_u = smem_u32(KS);
    uint32_t vs_u = smem_u32(VS);

    int bh = blockIdx.y;
    int b = bh >> 3, h = bh & 7;
    int tid = threadIdx.x, w = tid >> 5, lane = tid & 31;

#pragma unroll
    for (int j = 0; j < 2; j++) {
        int idx = tid + j * 512;
        int row = idx >> 4, d = (idx & 15) * 4;
        float4 q = *reinterpret_cast<const float4*>(
            g_q + (size_t)(b * 64 + row) * IND + h * 64 + d);
        q.x *= 8.f; q.y *= 8.f; q.z *= 8.f; q.w *= 8.f;
        *reinterpret_cast<float4*>(QS + row * 64 + d) = q;
    }

    int s0beg = blockIdx.x * CHUNK_KEYS;
    int s0end = min(S_TOT, s0beg + CHUNK_KEYS);
    int ntiles = (s0end - s0beg) >> 6;

    int ckey = tid >> 3, cpart = tid & 7;
    const char* kv_base = (const char*)(g_kv + (size_t)(b * S_TOT) * (2 * IND)) + h * 256;

#define ISSUE_TILE(t, buf) do { \
        const char* srcr = kv_base + (size_t)(s0beg + (t) * 64 + ckey) * 4096; \
        cp16(ks_u + ((buf) * 4352 + ckey * KS_STRIDE + cpart * 4) * 4,        srcr + cpart * 16); \
        cp16(ks_u + ((buf) * 4352 + ckey * KS_STRIDE + (cpart + 8) * 4) * 4,  srcr + (cpart + 8) * 16); \
        cp16(vs_u + ((buf) * 4096 + ckey * 64 + cpart * 4) * 4,               srcr + 2048 + cpart * 16); \
        cp16(vs_u + ((buf) * 4096 + ckey * 64 + (cpart + 8) * 4) * 4,         srcr + 2048 + (cpart + 8) * 16); \
        CP_COMMIT(); \
    } while (0)

    ISSUE_TILE(0, 0);

    int r0 = w * 4;
    float m[4], l[4];
    float2 o[4];
#pragma unroll
    for (int r = 0; r < 4; r++) { m[r] = -3.0e38f; l[r] = 0.f; o[r] = make_float2(0.f, 0.f); }
    int dlo = lane * 2;

    for (int t = 0; t < ntiles; t++) {
        int buf = t & 1;
        if (t + 1 < ntiles) { ISSUE_TILE(t + 1, (t + 1) & 1); CP_WAIT(1); }
        else                { CP_WAIT(0); }
        __syncthreads();

        float s0[4] = {0.f, 0.f, 0.f, 0.f};
        float s1[4] = {0.f, 0.f, 0.f, 0.f};
        const float* kr0 = KS + buf * 4352 + lane * KS_STRIDE;
        const float* kr1 = kr0 + 32 * KS_STRIDE;
#pragma unroll
        for (int db = 0; db < 16; db++) {
            float4 k0 = *reinterpret_cast<const float4*>(kr0 + db * 4);
            float4 k1 = *reinterpret_cast<const float4*>(kr1 + db * 4);
#pragma unroll
            for (int r = 0; r < 4; r++) {
                float4 qf = *reinterpret_cast<const float4*>(QS + (r0 + r) * 64 + db * 4);
                s0[r] += qf.x * k0.x + qf.y * k0.y + qf.z * k0.z + qf.w * k0.w;
                s1[r] += qf.x * k1.x + qf.y * k1.y + qf.z * k1.z + qf.w * k1.w;
            }
        }

        float alpha[4];
#pragma unroll
        for (int r = 0; r < 4; r++) {
            float tm = warpMax(fmaxf(s0[r], s1[r]));
            float mn = fmaxf(m[r], tm);
            float p0 = __expf(s0[r] - mn);
            float p1 = __expf(s1[r] - mn);
            alpha[r] = __expf(m[r] - mn);
            float psum = warpSum(p0 + p1);
            l[r] = l[r] * alpha[r] + psum;
            m[r] = mn;
            PS[(r0 + r) * PS_STRIDE + lane]      = p0;
            PS[(r0 + r) * PS_STRIDE + 32 + lane] = p1;
        }
        __syncwarp();

        const float* vb = VS + buf * 4096;
#pragma unroll
        for (int r = 0; r < 4; r++) { o[r].x *= alpha[r]; o[r].y *= alpha[r]; }
#pragma unroll
        for (int k4 = 0; k4 < 16; k4++) {
            float2 v0 = *reinterpret_cast<const float2*>(vb + (k4 * 4 + 0) * 64 + dlo);
            float2 v1 = *reinterpret_cast<const float2*>(vb + (k4 * 4 + 1) * 64 + dlo);
            float2 v2 = *reinterpret_cast<const float2*>(vb + (k4 * 4 + 2) * 64 + dlo);
            float2 v3 = *reinterpret_cast<const float2*>(vb + (k4 * 4 + 3) * 64 + dlo);
#pragma unroll
            for (int r = 0; r < 4; r++) {
                float4 pb = *reinterpret_cast<const float4*>(PS + (r0 + r) * PS_STRIDE + k4 * 4);
                o[r].x += pb.x * v0.x + pb.y * v1.x + pb.z * v2.x + pb.w * v3.x;
                o[r].y += pb.x * v0.y + pb.y * v1.y + pb.z * v2.y + pb.w * v3.y;
            }
        }
        __syncthreads();
    }

    int c = bh * NCHUNK + blockIdx.x;
#pragma unroll
    for (int r = 0; r < 4; r++) {
        int row = r0 + r;
        *reinterpret_cast<float2*>(g_po + ((size_t)c * 64 + row) * 64 + dlo) = o[r];
        if (lane == 0) { g_pm[c * 64 + row] = m[r]; g_pl[c * 64 + row] = l[r]; }
    }
#undef ISSUE_TILE
}

// ---------------- 6. merge split-KV partials ----------------
__global__ void __launch_bounds__(256) merge_kernel()
{
    int bh = blockIdx.x;
    int b = bh >> 3, h = bh & 7;
    int tid = threadIdx.x;
    int row = tid >> 2;
    int dp  = (tid & 3) * 16;

    float mx = -3.0e38f;
    for (int c = 0; c < NCHUNK; c++)
        mx = fmaxf(mx, g_pm[(bh * NCHUNK + c) * 64 + row]);

    float Ls = 0.f;
    float acc[16];
#pragma unroll
    for (int j = 0; j < 16; j++) acc[j] = 0.f;

    for (int c = 0; c < NCHUNK; c++) {
        int idx = (bh * NCHUNK + c) * 64 + row;
        float wgt = __expf(g_pm[idx] - mx);
        Ls += wgt * g_pl[idx];
        const float* po = g_po + (size_t)idx * 64 + dp;
#pragma unroll
        for (int j = 0; j < 16; j++) acc[j] += wgt * po[j];
    }
    float inv = 1.0f / Ls;
    float* dst = g_ao + (size_t)(b * 64 + row) * IND + h * 64 + dp;
#pragma unroll
    for (int j = 0; j < 16; j++) dst[j] = acc[j] * inv;
}

// ---------------- 7. out = attn_out @ Wout (vectorized: 4 cols x 2 rows per thread) ----------------
// 32768 threads = 128 blocks x 256. thread: n4 = (o&255)*4, rg = o>>8 (rows rg, rg+128)
__global__ void __launch_bounds__(256) out_gemm_kernel(
    const float* __restrict__ Wout, float* __restrict__ out)
{
    int o = blockIdx.x * 256 + threadIdx.x;
    int n4 = (o & 255) * 4;
    int rg = o >> 8;                       // 0..127
    float4 a0 = make_float4(0.f, 0.f, 0.f, 0.f);
    float4 a1 = make_float4(0.f, 0.f, 0.f, 0.f);
    const float* l0 = g_ao + (size_t)rg * IND;
    const float* l1 = g_ao + (size_t)(rg + 128) * IND;
    const float4* Wv = reinterpret_cast<const float4*>(Wout) + (n4 >> 2);
    for (int k = 0; k < IND; k++) {
        float4 wv = __ldg(Wv + (size_t)k * (DM / 4));
        float x0 = l0[k], x1 = l1[k];
        a0.x += x0 * wv.x; a0.y += x0 * wv.y; a0.z += x0 * wv.z; a0.w += x0 * wv.w;
        a1.x += x1 * wv.x; a1.y += x1 * wv.y; a1.z += x1 * wv.z; a1.w += x1 * wv.w;
    }
    *reinterpret_cast<float4*>(out + (size_t)rg * DM + n4)         = a0;
    *reinterpret_cast<float4*>(out + (size_t)(rg + 128) * DM + n4) = a1;
}

// ---------------- launch ----------------
extern "C" void kernel_launch(void* const* d_in, const int* in_sizes, int n_in,
                              void* d_out, int out_size)
{
    const float* x    = (const float*)d_in[0];
    const float* lat  = (const float*)d_in[1];
    const float* Wq   = (const float*)d_in[2];
    const float* Wkv  = (const float*)d_in[3];
    const float* Wout = (const float*)d_in[4];
    const float* gm   = (const float*)d_in[5];
    const float* bm   = (const float*)d_in[6];
    const float* gl   = (const float*)d_in[7];
    const float* bl   = (const float*)d_in[8];
    float* out = (float*)d_out;

    cudaFuncSetAttribute(kv_gemm_tc, cudaFuncAttributeMaxDynamicSharedMemorySize, SM_TOT);
    cudaFuncSetAttribute(attn_kernel, cudaFuncAttributeMaxDynamicSharedMemorySize, AQ_TOT_F * 4);

    prep_a_kernel<<<ROWS_KV / 8, 256>>>(x, lat, gm, bm, gl, bl);
    prep_w_kernel<<<dim3(32, 16), 256>>>(Wkv);
    q_gemm_kernel<<<16384 / 256, 256>>>(Wq);
    kv_gemm_tc<<<dim3(4, 129), 256, SM_TOT>>>();
    attn_kernel<<<dim3(NCHUNK, 32), 512, AQ_TOT_F * 4>>>();
    merge_kernel<<<32, 256>>>();
    out_gemm_kernel<<<32768 / 256, 256>>>(Wout, out);
}

// round 15
// speedup vs baseline: 1.2390x; 1.2390x over previous
#include <cuda_runtime.h>
#include <cuda_bf16.h>
#include <stdint.h>
#include <math.h>

#define BB 4
#define MM 8192
#define LL 64
#define DM 1024
#define IND 512
#define NH 8
#define DH 64
#define S_TOT (MM + LL)            // 8256
#define ROWS_X (BB * MM)           // 32768
#define ROWS_KV (BB * S_TOT)       // 33024
#define ROWS_L (BB * LL)           // 256
#define NCHUNK 9                   // 9 chunks: 8 x 960 keys + 1 x 576 keys
#define CHUNK_KEYS 960

// ---------------- scratch ----------------
__device__ float g_ln[ROWS_L * DM];
__device__ __nv_bfloat16 g_Ahi[(size_t)ROWS_KV * DM];
__device__ __nv_bfloat16 g_Alo[(size_t)ROWS_KV * DM];
__device__ __nv_bfloat16 g_Whi[(size_t)DM * DM];    // transposed: [n][k]
__device__ __nv_bfloat16 g_Wlo[(size_t)DM * DM];
__device__ float g_kv[(size_t)ROWS_KV * 2 * IND];
__device__ float g_q[ROWS_L * IND];
__device__ float g_po[BB * NH * NCHUNK * LL * DH];
__device__ float g_pm[BB * NH * NCHUNK * LL];
__device__ float g_pl[BB * NH * NCHUNK * LL];
__device__ float g_ao[ROWS_L * IND];

__device__ __forceinline__ float warpSum(float v) {
#pragma unroll
    for (int o = 16; o; o >>= 1) v += __shfl_xor_sync(0xffffffffu, v, o);
    return v;
}
__device__ __forceinline__ float warpMax(float v) {
#pragma unroll
    for (int o = 16; o; o >>= 1) v = fmaxf(v, __shfl_xor_sync(0xffffffffu, v, o));
    return v;
}

// ---------------- PTX helpers ----------------
__device__ __forceinline__ uint32_t smem_u32(const void* p) {
    uint32_t a;
    asm("{ .reg .u64 t; cvta.to.shared.u64 t, %1; cvt.u32.u64 %0, t; }" : "=r"(a) : "l"(p));
    return a;
}
__device__ __forceinline__ uint32_t elect_one() {
    uint32_t pred;
    asm volatile("{\n\t.reg .pred p;\n\telect.sync _|p, 0xFFFFFFFF;\n\tselp.b32 %0, 1, 0, p;\n\t}" : "=r"(pred));
    return pred;
}
__device__ __forceinline__ void cp16(uint32_t dst, const void* src) {
    asm volatile("cp.async.cg.shared.global [%0], [%1], 16;" :: "r"(dst), "l"(src));
}
#define CP_COMMIT() asm volatile("cp.async.commit_group;" ::: "memory")
#define CP_WAIT(n)  asm volatile("cp.async.wait_group %0;" :: "n"(n) : "memory")
#define CP_MBAR_ARRIVE(addr) \
    asm volatile("cp.async.mbarrier.arrive.noinc.shared::cta.b64 [%0];" :: "r"(addr) : "memory")
#define MBAR_INIT(addr, cnt) \
    asm volatile("mbarrier.init.shared.b64 [%0], %1;" :: "r"(addr), "r"(cnt) : "memory")
#define MBAR_WAIT(addr, parity) do { \
    uint32_t _m = (addr); uint32_t _p = (parity); uint32_t _done; \
    asm volatile("{\n\t.reg .pred p;\n\tmbarrier.try_wait.parity.acquire.cta.shared::cta.b64 p, [%1], %2;\n\tselp.b32 %0, 1, 0, p;\n\t}" \
        : "=r"(_done) : "r"(_m), "r"(_p) : "memory"); \
    if (!_done) { \
        asm volatile("{\n\t.reg .pred P1;\n\tWL_%=:\n\tmbarrier.try_wait.parity.acquire.cta.shared::cta.b64 P1, [%0], %1, 0x989680;\n\t@P1 bra.uni WD_%=;\n\tbra.uni WL_%=;\n\tWD_%=:\n\t}" \
            :: "r"(_m), "r"(_p) : "memory"); \
    } } while (0)
#define FENCE_ASYNC() asm volatile("fence.proxy.async.shared::cta;" ::: "memory")

#if defined(__CUDA_ARCH_FEAT_SM103_ALL) || defined(__CUDA_ARCH_FEAT_SM100_ALL)
#define HAS_TCGEN05 1
#else
#define HAS_TCGEN05 0
#endif

#if HAS_TCGEN05
#define TC_ALLOC(smem_addr, ncols) \
    asm volatile("tcgen05.alloc.cta_group::1.sync.aligned.shared::cta.b32 [%0], %1;" :: "r"(smem_addr), "r"(ncols) : "memory")
#define TC_DEALLOC(tmem, ncols) \
    asm volatile("tcgen05.dealloc.cta_group::1.sync.aligned.b32 %0, %1;" :: "r"(tmem), "r"(ncols))
#define TC_RELINQ() \
    asm volatile("tcgen05.relinquish_alloc_permit.cta_group::1.sync.aligned;")
#define TC_COMMIT(mbar) \
    asm volatile("tcgen05.commit.cta_group::1.mbarrier::arrive::one.shared::cluster.b64 [%0];" :: "r"(mbar) : "memory")
#define TC_FENCE_AFTER() asm volatile("tcgen05.fence::after_thread_sync;" ::: "memory")
#define TC_WAIT_LD() asm volatile("tcgen05.wait::ld.sync.aligned;" ::: "memory")

__device__ __forceinline__ void mma_f16_ss(uint32_t d, uint64_t ad, uint64_t bd,
                                           uint32_t idesc, uint32_t en) {
    asm volatile(
        "{\n\t.reg .pred p;\n\tsetp.ne.u32 p, %4, 0;\n\t"
        "tcgen05.mma.cta_group::1.kind::f16 [%0], %1, %2, %3, {%5, %5, %5, %5}, p;\n\t}"
        :: "r"(d), "l"(ad), "l"(bd), "r"(idesc), "r"(en), "r"(0u) : "memory");
}
#define LDTM_X32(r, addr) \
    asm volatile("tcgen05.ld.sync.aligned.32x32b.x32.b32 " \
        "{%0,%1,%2,%3,%4,%5,%6,%7,%8,%9,%10,%11,%12,%13,%14,%15," \
        "%16,%17,%18,%19,%20,%21,%22,%23,%24,%25,%26,%27,%28,%29,%30,%31}, [%32];" \
        : "=r"((r)[0]),"=r"((r)[1]),"=r"((r)[2]),"=r"((r)[3]),"=r"((r)[4]),"=r"((r)[5]),"=r"((r)[6]),"=r"((r)[7]), \
          "=r"((r)[8]),"=r"((r)[9]),"=r"((r)[10]),"=r"((r)[11]),"=r"((r)[12]),"=r"((r)[13]),"=r"((r)[14]),"=r"((r)[15]), \
          "=r"((r)[16]),"=r"((r)[17]),"=r"((r)[18]),"=r"((r)[19]),"=r"((r)[20]),"=r"((r)[21]),"=r"((r)[22]),"=r"((r)[23]), \
          "=r"((r)[24]),"=r"((r)[25]),"=r"((r)[26]),"=r"((r)[27]),"=r"((r)[28]),"=r"((r)[29]),"=r"((r)[30]),"=r"((r)[31]) \
        : "r"(addr))
#endif

// SW64 K-major desc: layout=4, version=1, SBO=32 (512B atom stride), LBO=1
__device__ __forceinline__ uint64_t make_desc64(uint32_t saddr) {
    const uint64_t base = (uint64_t(4) << 61) | (uint64_t(1) << 46) | (uint64_t(32) << 32) | (uint64_t(1) << 16);
    return base | ((uint64_t)(saddr >> 4) & 0x3FFF);
}
// idesc: F32 accum, BF16 a/b, N=256, M=128
#define KV_IDESC ((1u << 4) | (1u << 7) | (1u << 10) | (32u << 17) | (8u << 24))

// ---------------- 1. LN + bf16 hi/lo split, warp-per-row ----------------
__global__ void __launch_bounds__(256) prep_a_kernel(
    const float* __restrict__ x, const float* __restrict__ lat,
    const float* __restrict__ gm, const float* __restrict__ bm,
    const float* __restrict__ gl, const float* __restrict__ bl)
{
    int wid = threadIdx.x >> 5, lane = threadIdx.x & 31;
    int row = blockIdx.x * 8 + wid;
    bool isx = row < ROWS_X;
    const float4* src = reinterpret_cast<const float4*>(
        isx ? (x + (size_t)row * DM) : (lat + (size_t)(row - ROWS_X) * DM));

    float4 v[8];
    float s = 0.f, sq = 0.f;
#pragma unroll
    for (int i = 0; i < 8; i++) {
        v[i] = src[lane + 32 * i];
        s  += v[i].x + v[i].y + v[i].z + v[i].w;
        sq += v[i].x * v[i].x + v[i].y * v[i].y + v[i].z * v[i].z + v[i].w * v[i].w;
    }
    s = warpSum(s); sq = warpSum(sq);
    float mean = s * (1.0f / 1024.0f);
    float var  = sq * (1.0f / 1024.0f) - mean * mean;
    float rstd = rsqrtf(var + 1e-5f);

    const float4* gp = reinterpret_cast<const float4*>(isx ? gm : gl);
    const float4* bp = reinterpret_cast<const float4*>(isx ? bm : bl);

    int arow;
    float* lnrow = nullptr;
    if (isx) {
        int bb = row >> 13, ss = row & 8191;
        arow = bb * S_TOT + ss;
    } else {
        int lr = row - ROWS_X;
        int bb = lr >> 6, j = lr & 63;
        arow = bb * S_TOT + MM + j;
        lnrow = g_ln + (size_t)lr * DM;
    }
    uint2* hdst = reinterpret_cast<uint2*>(g_Ahi + (size_t)arow * DM);
    uint2* ldst = reinterpret_cast<uint2*>(g_Alo + (size_t)arow * DM);

#pragma unroll
    for (int i = 0; i < 8; i++) {
        float4 g4 = gp[lane + 32 * i];
        float4 b4 = bp[lane + 32 * i];
        float4 o;
        o.x = (v[i].x - mean) * rstd * g4.x + b4.x;
        o.y = (v[i].y - mean) * rstd * g4.y + b4.y;
        o.z = (v[i].z - mean) * rstd * g4.z + b4.z;
        o.w = (v[i].w - mean) * rstd * g4.w + b4.w;
        if (lnrow) reinterpret_cast<float4*>(lnrow)[lane + 32 * i] = o;

        __nv_bfloat16 hx = __float2bfloat16(o.x), hy = __float2bfloat16(o.y);
        __nv_bfloat16 hz = __float2bfloat16(o.z), hw = __float2bfloat16(o.w);
        float rx = o.x - __bfloat162float(hx), ry = o.y - __bfloat162float(hy);
        float rz = o.z - __bfloat162float(hz), rw = o.w - __bfloat162float(hw);
        __nv_bfloat162 h01 = __nv_bfloat162(hx, hy), h23 = __nv_bfloat162(hz, hw);
        __nv_bfloat162 l01 = __floats2bfloat162_rn(rx, ry), l23 = __floats2bfloat162_rn(rz, rw);
        uint2 uh, ul;
        uh.x = *reinterpret_cast<uint32_t*>(&h01); uh.y = *reinterpret_cast<uint32_t*>(&h23);
        ul.x = *reinterpret_cast<uint32_t*>(&l01); ul.y = *reinterpret_cast<uint32_t*>(&l23);
        hdst[lane + 32 * i] = uh;
        ldst[lane + 32 * i] = ul;
    }
}

// ---------------- 2. W transpose + hi/lo split ----------------
__global__ void __launch_bounds__(256) prep_w_kernel(const float* __restrict__ Wkv)
{
    __shared__ float s[64][33];
    int n0 = blockIdx.x * 32;
    int k0 = blockIdx.y * 64;
    int tid = threadIdx.x;

#pragma unroll
    for (int it = 0; it < 8; it++) {
        int idx = it * 256 + tid;
        int i = idx >> 5, j = idx & 31;
        s[i][j] = Wkv[(size_t)(k0 + i) * (2 * IND) + n0 + j];
    }
    __syncthreads();

#pragma unroll
    for (int it = 0; it < 4; it++) {
        int idx = it * 256 + tid;
        int j  = idx >> 5;
        int ii = (idx & 31) * 2;
        float v0 = s[ii][j], v1 = s[ii + 1][j];
        __nv_bfloat16 h0 = __float2bfloat16(v0), h1 = __float2bfloat16(v1);
        float r0 = v0 - __bfloat162float(h0), r1 = v1 - __bfloat162float(h1);
        __nv_bfloat162 hp = __nv_bfloat162(h0, h1);
        __nv_bfloat162 lp = __floats2bfloat162_rn(r0, r1);
        size_t off = ((size_t)(n0 + j) * DM + k0 + ii) >> 1;
        reinterpret_cast<uint32_t*>(g_Whi)[off] = *reinterpret_cast<uint32_t*>(&hp);
        reinterpret_cast<uint32_t*>(g_Wlo)[off] = *reinterpret_cast<uint32_t*>(&lp);
    }
}

// ---------------- 3. q = ln @ Wq (4 cols x 1 row per thread, full grid) ----------------
// 32768 threads = 128 blocks. n4 = (o&127)*4, rg = o>>7 (0..255)
__global__ void __launch_bounds__(256) q_gemm_kernel(const float* __restrict__ Wq)
{
    int o = blockIdx.x * 256 + threadIdx.x;
    int n4 = (o & 127) * 4;
    int rg = o >> 7;                       // 0..255
    float4 a0 = make_float4(0.f, 0.f, 0.f, 0.f);
    const float* l0 = g_ln + (size_t)rg * DM;
    const float4* Wv = reinterpret_cast<const float4*>(Wq) + (n4 >> 2);
    for (int k = 0; k < DM; k++) {
        float4 wv = __ldg(Wv + (size_t)k * (IND / 4));
        float x0 = l0[k];
        a0.x += x0 * wv.x; a0.y += x0 * wv.y; a0.z += x0 * wv.z; a0.w += x0 * wv.w;
    }
    *reinterpret_cast<float4*>(g_q + (size_t)rg * IND + n4) = a0;
}

// ---------------- 4. KV GEMM (unchanged — at LTS floor) ----------------
#define OFF_AHI 0
#define OFF_ALO 16384
#define OFF_WHI 32768
#define OFF_WLO 49152
#define STAGE_BYTES 65536
#define NSTAGE 3
#define SM_TM   0
#define SM_MB   64
#define SM_DATA 1024
#define SM_TOT  (SM_DATA + NSTAGE * STAGE_BYTES)

__global__ void __launch_bounds__(256) kv_gemm_tc()
{
#if HAS_TCGEN05
    extern __shared__ char smem[];
    uint32_t sb = smem_u32(smem);
    int tid = threadIdx.x, wid = tid >> 5;
    int ntile = blockIdx.x, mtile = blockIdx.y;

    if (wid == 0) { TC_ALLOC(sb + SM_TM, 512); TC_RELINQ(); }
    if (tid == 0) {
#pragma unroll
        for (int st = 0; st < NSTAGE; st++) {
            MBAR_INIT(sb + SM_MB + st * 16, 256);
            MBAR_INIT(sb + SM_MB + st * 16 + 8, 1);
        }
    }
    __syncthreads();
    uint32_t tmem;
    asm volatile("ld.shared.b32 %0, [%1];" : "=r"(tmem) : "r"(sb + SM_TM));

    const char* Ah = (const char*)g_Ahi + (size_t)(mtile * 256) * 2048;
    const char* Al = (const char*)g_Alo + (size_t)(mtile * 256) * 2048;
    const char* Wh = (const char*)g_Whi + (size_t)(ntile * 256) * 2048;
    const char* Wl = (const char*)g_Wlo + (size_t)(ntile * 256) * 2048;

    uint32_t c_src[4], c_dst[4];
#pragma unroll
    for (int it = 0; it < 4; it++) {
        int idx = it * 256 + tid;
        int row = idx >> 2, cb = idx & 3;
        c_src[it] = (uint32_t)(row * 2048 + cb * 16);
        uint32_t bo = (uint32_t)(row * 64 + cb * 16);
        c_dst[it] = bo ^ ((bo >> 3) & 0x30);
    }

#define FILL_STAGE(st, kc) do { \
        uint32_t sbase = sb + SM_DATA + (st) * STAGE_BYTES; \
        uint32_t koff = (uint32_t)(kc) * 64; \
        _Pragma("unroll") \
        for (int it = 0; it < 4; it++) { \
            cp16(sbase + OFF_AHI + c_dst[it], Ah + c_src[it] + koff); \
            cp16(sbase + OFF_ALO + c_dst[it], Al + c_src[it] + koff); \
            cp16(sbase + OFF_WHI + c_dst[it], Wh + c_src[it] + koff); \
            cp16(sbase + OFF_WLO + c_dst[it], Wl + c_src[it] + koff); \
        } \
        CP_MBAR_ARRIVE(sb + SM_MB + (st) * 16); \
    } while (0)

    FILL_STAGE(0, 0);
    FILL_STAGE(1, 1);
    FILL_STAGE(2, 2);

    int fc[NSTAGE] = {0, 0, 0};
    int ec[NSTAGE] = {0, 0, 0};

    for (int kc = 0; kc < 32; kc++) {
        int st = kc - (kc / 3) * 3;

        if (wid == 0 && elect_one()) {
            MBAR_WAIT(sb + SM_MB + st * 16, (uint32_t)(fc[st] & 1));
            fc[st]++;
            FENCE_ASYNC();
            uint32_t sbase = sb + SM_DATA + st * STAGE_BYTES;
            uint64_t ahd = make_desc64(sbase + OFF_AHI);
            uint64_t ald = make_desc64(sbase + OFF_ALO);
            uint64_t whd = make_desc64(sbase + OFF_WHI);
            uint64_t wld = make_desc64(sbase + OFF_WLO);
#pragma unroll
            for (int sub = 0; sub < 2; sub++) {
                uint32_t dtm = tmem + sub * 256;
                uint64_t aoff = (uint64_t)(sub * 512);
#pragma unroll
                for (int s = 0; s < 2; s++) {
                    uint32_t en = !(kc == 0 && s == 0);
                    mma_f16_ss(dtm, ahd + aoff + s * 2, whd + s * 2, KV_IDESC, en);
                }
#pragma unroll
                for (int s = 0; s < 2; s++)
                    mma_f16_ss(dtm, ahd + aoff + s * 2, wld + s * 2, KV_IDESC, 1);
#pragma unroll
                for (int s = 0; s < 2; s++)
                    mma_f16_ss(dtm, ald + aoff + s * 2, whd + s * 2, KV_IDESC, 1);
            }
            TC_COMMIT(sb + SM_MB + st * 16 + 8);
        }

        if (kc >= 1 && kc + 2 <= 31) {
            int stp = (kc + 2) - ((kc + 2) / 3) * 3;
            MBAR_WAIT(sb + SM_MB + stp * 16 + 8, (uint32_t)(ec[stp] & 1));
            ec[stp]++;
            FILL_STAGE(stp, kc + 2);
        }
    }

#pragma unroll
    for (int st = 0; st < NSTAGE; st++) {
        MBAR_WAIT(sb + SM_MB + st * 16 + 8, (uint32_t)(ec[st] & 1));
        ec[st]++;
    }
    TC_FENCE_AFTER();

    {
        int lane = tid & 31;
        int half = wid >> 2;
        int wiw  = wid & 3;
        uint32_t tbase = tmem + half * 256;
        size_t rowg = (size_t)(mtile * 256 + half * 128 + wiw * 32 + lane);
        float* dst = g_kv + rowg * (2 * IND) + ntile * 256;
#pragma unroll
        for (int cb = 0; cb < 8; cb++) {
            uint32_t r[32];
            LDTM_X32(r, tbase + cb * 32);
            TC_WAIT_LD();
#pragma unroll
            for (int j = 0; j < 32; j += 4) {
                uint4 v;
                v.x = r[j]; v.y = r[j + 1]; v.z = r[j + 2]; v.w = r[j + 3];
                *reinterpret_cast<uint4*>(dst + cb * 32 + j) = v;
            }
        }
    }
    __syncthreads();
    if (wid == 0) TC_DEALLOC(tmem, 512);
#undef FILL_STAGE
#else
    int tid = threadIdx.x;
    int ntile = blockIdx.x, mtile = blockIdx.y;
    for (int i = tid; i < 256 * 256; i += 256) {
        int r = i >> 8, cc = i & 255;
        size_t row = (size_t)mtile * 256 + r;
        size_t col = (size_t)ntile * 256 + cc;
        float acc = 0.f;
        for (int k = 0; k < DM; k++) {
            float a = __bfloat162float(g_Ahi[row * DM + k]) + __bfloat162float(g_Alo[row * DM + k]);
            float w = __bfloat162float(g_Whi[col * DM + k]) + __bfloat162float(g_Wlo[col * DM + k]);
            acc += a * w;
        }
        g_kv[row * (2 * IND) + col] = acc;
    }
#endif
}

// ---------------- 5. split-KV flash attention: 64-key tiles, 960-key chunks (1 wave) ----------------
#define AQ_QS 0
#define AQ_KS 4096
#define AQ_VS 12800
#define AQ_PS 20992
#define AQ_TOT_F 25344
#define KS_STRIDE 68
#define PS_STRIDE 68

__global__ void __launch_bounds__(512) attn_kernel()
{
    extern __shared__ float sm[];
    float* QS = sm + AQ_QS;
    float* KS = sm + AQ_KS;
    float* VS = sm + AQ_VS;
    float* PS = sm + AQ_PS;
    uint32_t ks_u = smem_u32(KS);
    uint32_t vs_u = smem_u32(VS);

    int bh = blockIdx.y;
    int b = bh >> 3, h = bh & 7;
    int tid = threadIdx.x, w = tid >> 5, lane = tid & 31;

#pragma unroll
    for (int j = 0; j < 2; j++) {
        int idx = tid + j * 512;
        int row = idx >> 4, d = (idx & 15) * 4;
        float4 q = *reinterpret_cast<const float4*>(
            g_q + (size_t)(b * 64 + row) * IND + h * 64 + d);
        q.x *= 8.f; q.y *= 8.f; q.z *= 8.f; q.w *= 8.f;
        *reinterpret_cast<float4*>(QS + row * 64 + d) = q;
    }

    int s0beg = blockIdx.x * CHUNK_KEYS;
    int s0end = min(S_TOT, s0beg + CHUNK_KEYS);
    int ntiles = (s0end - s0beg) >> 6;

    int ckey = tid >> 3, cpart = tid & 7;
    const char* kv_base = (const char*)(g_kv + (size_t)(b * S_TOT) * (2 * IND)) + h * 256;

#define ISSUE_TILE(t, buf) do { \
        const char* srcr = kv_base + (size_t)(s0beg + (t) * 64 + ckey) * 4096; \
        cp16(ks_u + ((buf) * 4352 + ckey * KS_STRIDE + cpart * 4) * 4,        srcr + cpart * 16); \
        cp16(ks_u + ((buf) * 4352 + ckey * KS_STRIDE + (cpart + 8) * 4) * 4,  srcr + (cpart + 8) * 16); \
        cp16(vs_u + ((buf) * 4096 + ckey * 64 + cpart * 4) * 4,               srcr + 2048 + cpart * 16); \
        cp16(vs_u + ((buf) * 4096 + ckey * 64 + (cpart + 8) * 4) * 4,         srcr + 2048 + (cpart + 8) * 16); \
        CP_COMMIT(); \
    } while (0)

    ISSUE_TILE(0, 0);

    int r0 = w * 4;
    float m[4], l[4];
    float2 o[4];
#pragma unroll
    for (int r = 0; r < 4; r++) { m[r] = -3.0e38f; l[r] = 0.f; o[r] = make_float2(0.f, 0.f); }
    int dlo = lane * 2;

    for (int t = 0; t < ntiles; t++) {
        int buf = t & 1;
        if (t + 1 < ntiles) { ISSUE_TILE(t + 1, (t + 1) & 1); CP_WAIT(1); }
        else                { CP_WAIT(0); }
        __syncthreads();

        float s0[4] = {0.f, 0.f, 0.f, 0.f};
        float s1[4] = {0.f, 0.f, 0.f, 0.f};
        const float* kr0 = KS + buf * 4352 + lane * KS_STRIDE;
        const float* kr1 = kr0 + 32 * KS_STRIDE;
#pragma unroll
        for (int db = 0; db < 16; db++) {
            float4 k0 = *reinterpret_cast<const float4*>(kr0 + db * 4);
            float4 k1 = *reinterpret_cast<const float4*>(kr1 + db * 4);
#pragma unroll
            for (int r = 0; r < 4; r++) {
                float4 qf = *reinterpret_cast<const float4*>(QS + (r0 + r) * 64 + db * 4);
                s0[r] += qf.x * k0.x + qf.y * k0.y + qf.z * k0.z + qf.w * k0.w;
                s1[r] += qf.x * k1.x + qf.y * k1.y + qf.z * k1.z + qf.w * k1.w;
            }
        }

        float alpha[4];
#pragma unroll
        for (int r = 0; r < 4; r++) {
            float tm = warpMax(fmaxf(s0[r], s1[r]));
            float mn = fmaxf(m[r], tm);
            float p0 = __expf(s0[r] - mn);
            float p1 = __expf(s1[r] - mn);
            alpha[r] = __expf(m[r] - mn);
            float psum = warpSum(p0 + p1);
            l[r] = l[r] * alpha[r] + psum;
            m[r] = mn;
            PS[(r0 + r) * PS_STRIDE + lane]      = p0;
            PS[(r0 + r) * PS_STRIDE + 32 + lane] = p1;
        }
        __syncwarp();

        const float* vb = VS + buf * 4096;
#pragma unroll
        for (int r = 0; r < 4; r++) { o[r].x *= alpha[r]; o[r].y *= alpha[r]; }
#pragma unroll
        for (int k4 = 0; k4 < 16; k4++) {
            float2 v0 = *reinterpret_cast<const float2*>(vb + (k4 * 4 + 0) * 64 + dlo);
            float2 v1 = *reinterpret_cast<const float2*>(vb + (k4 * 4 + 1) * 64 + dlo);
            float2 v2 = *reinterpret_cast<const float2*>(vb + (k4 * 4 + 2) * 64 + dlo);
            float2 v3 = *reinterpret_cast<const float2*>(vb + (k4 * 4 + 3) * 64 + dlo);
#pragma unroll
            for (int r = 0; r < 4; r++) {
                float4 pb = *reinterpret_cast<const float4*>(PS + (r0 + r) * PS_STRIDE + k4 * 4);
                o[r].x += pb.x * v0.x + pb.y * v1.x + pb.z * v2.x + pb.w * v3.x;
                o[r].y += pb.x * v0.y + pb.y * v1.y + pb.z * v2.y + pb.w * v3.y;
            }
        }
        __syncthreads();
    }

    int c = bh * NCHUNK + blockIdx.x;
#pragma unroll
    for (int r = 0; r < 4; r++) {
        int row = r0 + r;
        *reinterpret_cast<float2*>(g_po + ((size_t)c * 64 + row) * 64 + dlo) = o[r];
        if (lane == 0) { g_pm[c * 64 + row] = m[r]; g_pl[c * 64 + row] = l[r]; }
    }
#undef ISSUE_TILE
}

// ---------------- 6. merge split-KV partials ----------------
__global__ void __launch_bounds__(256) merge_kernel()
{
    int bh = blockIdx.x;
    int b = bh >> 3, h = bh & 7;
    int tid = threadIdx.x;
    int row = tid >> 2;
    int dp  = (tid & 3) * 16;

    float mx = -3.0e38f;
    for (int c = 0; c < NCHUNK; c++)
        mx = fmaxf(mx, g_pm[(bh * NCHUNK + c) * 64 + row]);

    float Ls = 0.f;
    float acc[16];
#pragma unroll
    for (int j = 0; j < 16; j++) acc[j] = 0.f;

    for (int c = 0; c < NCHUNK; c++) {
        int idx = (bh * NCHUNK + c) * 64 + row;
        float wgt = __expf(g_pm[idx] - mx);
        Ls += wgt * g_pl[idx];
        const float* po = g_po + (size_t)idx * 64 + dp;
#pragma unroll
        for (int j = 0; j < 16; j++) acc[j] += wgt * po[j];
    }
    float inv = 1.0f / Ls;
    float* dst = g_ao + (size_t)(b * 64 + row) * IND + h * 64 + dp;
#pragma unroll
    for (int j = 0; j < 16; j++) dst[j] = acc[j] * inv;
}

// ---------------- 7. out = attn_out @ Wout (4 cols x 1 row per thread, full grid) ----------------
// 65536 threads = 256 blocks. n4 = (o&255)*4, rg = o>>8 (0..255)
__global__ void __launch_bounds__(256) out_gemm_kernel(
    const float* __restrict__ Wout, float* __restrict__ out)
{
    int o = blockIdx.x * 256 + threadIdx.x;
    int n4 = (o & 255) * 4;
    int rg = o >> 8;                       // 0..255
    float4 a0 = make_float4(0.f, 0.f, 0.f, 0.f);
    const float* l0 = g_ao + (size_t)rg * IND;
    const float4* Wv = reinterpret_cast<const float4*>(Wout) + (n4 >> 2);
    for (int k = 0; k < IND; k++) {
        float4 wv = __ldg(Wv + (size_t)k * (DM / 4));
        float x0 = l0[k];
        a0.x += x0 * wv.x; a0.y += x0 * wv.y; a0.z += x0 * wv.z; a0.w += x0 * wv.w;
    }
    *reinterpret_cast<float4*>(out + (size_t)rg * DM + n4) = a0;
}

// ---------------- launch ----------------
extern "C" void kernel_launch(void* const* d_in, const int* in_sizes, int n_in,
                              void* d_out, int out_size)
{
    const float* x    = (const float*)d_in[0];
    const float* lat  = (const float*)d_in[1];
    const float* Wq   = (const float*)d_in[2];
    const float* Wkv  = (const float*)d_in[3];
    const float* Wout = (const float*)d_in[4];
    const float* gm   = (const float*)d_in[5];
    const float* bm   = (const float*)d_in[6];
    const float* gl   = (const float*)d_in[7];
    const float* bl   = (const float*)d_in[8];
    float* out = (float*)d_out;

    cudaFuncSetAttribute(kv_gemm_tc, cudaFuncAttributeMaxDynamicSharedMemorySize, SM_TOT);
    cudaFuncSetAttribute(attn_kernel, cudaFuncAttributeMaxDynamicSharedMemorySize, AQ_TOT_F * 4);

    prep_a_kernel<<<ROWS_KV / 8, 256>>>(x, lat, gm, bm, gl, bl);
    prep_w_kernel<<<dim3(32, 16), 256>>>(Wkv);
    q_gemm_kernel<<<32768 / 256, 256>>>(Wq);
    kv_gemm_tc<<<dim3(4, 129), 256, SM_TOT>>>();
    attn_kernel<<<dim3(NCHUNK, 32), 512, AQ_TOT_F * 4>>>();
    merge_kernel<<<32, 256>>>();
    out_gemm_kernel<<<65536 / 256, 256>>>(Wout, out);
}

// round 16
// speedup vs baseline: 1.7035x; 1.3749x over previous
#include <cuda_runtime.h>
#include <cuda_bf16.h>
#include <stdint.h>
#include <math.h>

#define BB 4
#define MM 8192
#define LL 64
#define DM 1024
#define IND 512
#define NH 8
#define DH 64
#define S_TOT (MM + LL)            // 8256
#define ROWS_X (BB * MM)           // 32768
#define ROWS_KV (BB * S_TOT)       // 33024
#define ROWS_L (BB * LL)           // 256
#define NCHUNK 9                   // 8 x 960 keys + 1 x 576 keys
#define CHUNK_KEYS 960

// ---------------- scratch ----------------
__device__ float g_ln[ROWS_L * DM];
__device__ __nv_bfloat16 g_Ahi[(size_t)ROWS_KV * DM];
__device__ __nv_bfloat16 g_Alo[(size_t)ROWS_KV * DM];
__device__ __nv_bfloat16 g_Whi[(size_t)DM * DM];    // transposed: [n][k]
__device__ __nv_bfloat16 g_Wlo[(size_t)DM * DM];
__device__ float g_kv[(size_t)ROWS_KV * 2 * IND];
__device__ float g_q[ROWS_L * IND];
__device__ float g_qp[4 * ROWS_L * IND];            // q split-K partials
__device__ float g_outp[2 * ROWS_L * DM];           // out split-K partials
__device__ float g_po[BB * NH * NCHUNK * LL * DH];
__device__ float g_pm[BB * NH * NCHUNK * LL];
__device__ float g_pl[BB * NH * NCHUNK * LL];
__device__ float g_ao[ROWS_L * IND];

__device__ __forceinline__ float warpSum(float v) {
#pragma unroll
    for (int o = 16; o; o >>= 1) v += __shfl_xor_sync(0xffffffffu, v, o);
    return v;
}
__device__ __forceinline__ float warpMax(float v) {
#pragma unroll
    for (int o = 16; o; o >>= 1) v = fmaxf(v, __shfl_xor_sync(0xffffffffu, v, o));
    return v;
}

// ---------------- PTX helpers ----------------
__device__ __forceinline__ uint32_t smem_u32(const void* p) {
    uint32_t a;
    asm("{ .reg .u64 t; cvta.to.shared.u64 t, %1; cvt.u32.u64 %0, t; }" : "=r"(a) : "l"(p));
    return a;
}
__device__ __forceinline__ uint32_t elect_one() {
    uint32_t pred;
    asm volatile("{\n\t.reg .pred p;\n\telect.sync _|p, 0xFFFFFFFF;\n\tselp.b32 %0, 1, 0, p;\n\t}" : "=r"(pred));
    return pred;
}
__device__ __forceinline__ void cp16(uint32_t dst, const void* src) {
    asm volatile("cp.async.cg.shared.global [%0], [%1], 16;" :: "r"(dst), "l"(src));
}
#define CP_COMMIT() asm volatile("cp.async.commit_group;" ::: "memory")
#define CP_WAIT(n)  asm volatile("cp.async.wait_group %0;" :: "n"(n) : "memory")
#define CP_MBAR_ARRIVE(addr) \
    asm volatile("cp.async.mbarrier.arrive.noinc.shared::cta.b64 [%0];" :: "r"(addr) : "memory")
#define MBAR_INIT(addr, cnt) \
    asm volatile("mbarrier.init.shared.b64 [%0], %1;" :: "r"(addr), "r"(cnt) : "memory")
#define MBAR_WAIT(addr, parity) do { \
    uint32_t _m = (addr); uint32_t _p = (parity); uint32_t _done; \
    asm volatile("{\n\t.reg .pred p;\n\tmbarrier.try_wait.parity.acquire.cta.shared::cta.b64 p, [%1], %2;\n\tselp.b32 %0, 1, 0, p;\n\t}" \
        : "=r"(_done) : "r"(_m), "r"(_p) : "memory"); \
    if (!_done) { \
        asm volatile("{\n\t.reg .pred P1;\n\tWL_%=:\n\tmbarrier.try_wait.parity.acquire.cta.shared::cta.b64 P1, [%0], %1, 0x989680;\n\t@P1 bra.uni WD_%=;\n\tbra.uni WL_%=;\n\tWD_%=:\n\t}" \
            :: "r"(_m), "r"(_p) : "memory"); \
    } } while (0)
#define FENCE_ASYNC() asm volatile("fence.proxy.async.shared::cta;" ::: "memory")

#if defined(__CUDA_ARCH_FEAT_SM103_ALL) || defined(__CUDA_ARCH_FEAT_SM100_ALL)
#define HAS_TCGEN05 1
#else
#define HAS_TCGEN05 0
#endif

#if HAS_TCGEN05
#define TC_ALLOC(smem_addr, ncols) \
    asm volatile("tcgen05.alloc.cta_group::1.sync.aligned.shared::cta.b32 [%0], %1;" :: "r"(smem_addr), "r"(ncols) : "memory")
#define TC_DEALLOC(tmem, ncols) \
    asm volatile("tcgen05.dealloc.cta_group::1.sync.aligned.b32 %0, %1;" :: "r"(tmem), "r"(ncols))
#define TC_RELINQ() \
    asm volatile("tcgen05.relinquish_alloc_permit.cta_group::1.sync.aligned;")
#define TC_COMMIT(mbar) \
    asm volatile("tcgen05.commit.cta_group::1.mbarrier::arrive::one.shared::cluster.b64 [%0];" :: "r"(mbar) : "memory")
#define TC_FENCE_AFTER() asm volatile("tcgen05.fence::after_thread_sync;" ::: "memory")
#define TC_WAIT_LD() asm volatile("tcgen05.wait::ld.sync.aligned;" ::: "memory")

__device__ __forceinline__ void mma_f16_ss(uint32_t d, uint64_t ad, uint64_t bd,
                                           uint32_t idesc, uint32_t en) {
    asm volatile(
        "{\n\t.reg .pred p;\n\tsetp.ne.u32 p, %4, 0;\n\t"
        "tcgen05.mma.cta_group::1.kind::f16 [%0], %1, %2, %3, {%5, %5, %5, %5}, p;\n\t}"
        :: "r"(d), "l"(ad), "l"(bd), "r"(idesc), "r"(en), "r"(0u) : "memory");
}
#define LDTM_X32(r, addr) \
    asm volatile("tcgen05.ld.sync.aligned.32x32b.x32.b32 " \
        "{%0,%1,%2,%3,%4,%5,%6,%7,%8,%9,%10,%11,%12,%13,%14,%15," \
        "%16,%17,%18,%19,%20,%21,%22,%23,%24,%25,%26,%27,%28,%29,%30,%31}, [%32];" \
        : "=r"((r)[0]),"=r"((r)[1]),"=r"((r)[2]),"=r"((r)[3]),"=r"((r)[4]),"=r"((r)[5]),"=r"((r)[6]),"=r"((r)[7]), \
          "=r"((r)[8]),"=r"((r)[9]),"=r"((r)[10]),"=r"((r)[11]),"=r"((r)[12]),"=r"((r)[13]),"=r"((r)[14]),"=r"((r)[15]), \
          "=r"((r)[16]),"=r"((r)[17]),"=r"((r)[18]),"=r"((r)[19]),"=r"((r)[20]),"=r"((r)[21]),"=r"((r)[22]),"=r"((r)[23]), \
          "=r"((r)[24]),"=r"((r)[25]),"=r"((r)[26]),"=r"((r)[27]),"=r"((r)[28]),"=r"((r)[29]),"=r"((r)[30]),"=r"((r)[31]) \
        : "r"(addr))
#endif

// SW64 K-major desc: layout=4, version=1, SBO=32, LBO=1
__device__ __forceinline__ uint64_t make_desc64(uint32_t saddr) {
    const uint64_t base = (uint64_t(4) << 61) | (uint64_t(1) << 46) | (uint64_t(32) << 32) | (uint64_t(1) << 16);
    return base | ((uint64_t)(saddr >> 4) & 0x3FFF);
}
#define KV_IDESC ((1u << 4) | (1u << 7) | (1u << 10) | (32u << 17) | (8u << 24))

// ---------------- 1. LN + bf16 hi/lo split, warp-per-row ----------------
__global__ void __launch_bounds__(256) prep_a_kernel(
    const float* __restrict__ x, const float* __restrict__ lat,
    const float* __restrict__ gm, const float* __restrict__ bm,
    const float* __restrict__ gl, const float* __restrict__ bl)
{
    int wid = threadIdx.x >> 5, lane = threadIdx.x & 31;
    int row = blockIdx.x * 8 + wid;
    bool isx = row < ROWS_X;
    const float4* src = reinterpret_cast<const float4*>(
        isx ? (x + (size_t)row * DM) : (lat + (size_t)(row - ROWS_X) * DM));

    float4 v[8];
    float s = 0.f, sq = 0.f;
#pragma unroll
    for (int i = 0; i < 8; i++) {
        v[i] = src[lane + 32 * i];
        s  += v[i].x + v[i].y + v[i].z + v[i].w;
        sq += v[i].x * v[i].x + v[i].y * v[i].y + v[i].z * v[i].z + v[i].w * v[i].w;
    }
    s = warpSum(s); sq = warpSum(sq);
    float mean = s * (1.0f / 1024.0f);
    float var  = sq * (1.0f / 1024.0f) - mean * mean;
    float rstd = rsqrtf(var + 1e-5f);

    const float4* gp = reinterpret_cast<const float4*>(isx ? gm : gl);
    const float4* bp = reinterpret_cast<const float4*>(isx ? bm : bl);

    int arow;
    float* lnrow = nullptr;
    if (isx) {
        int bb = row >> 13, ss = row & 8191;
        arow = bb * S_TOT + ss;
    } else {
        int lr = row - ROWS_X;
        int bb = lr >> 6, j = lr & 63;
        arow = bb * S_TOT + MM + j;
        lnrow = g_ln + (size_t)lr * DM;
    }
    uint2* hdst = reinterpret_cast<uint2*>(g_Ahi + (size_t)arow * DM);
    uint2* ldst = reinterpret_cast<uint2*>(g_Alo + (size_t)arow * DM);

#pragma unroll
    for (int i = 0; i < 8; i++) {
        float4 g4 = gp[lane + 32 * i];
        float4 b4 = bp[lane + 32 * i];
        float4 o;
        o.x = (v[i].x - mean) * rstd * g4.x + b4.x;
        o.y = (v[i].y - mean) * rstd * g4.y + b4.y;
        o.z = (v[i].z - mean) * rstd * g4.z + b4.z;
        o.w = (v[i].w - mean) * rstd * g4.w + b4.w;
        if (lnrow) reinterpret_cast<float4*>(lnrow)[lane + 32 * i] = o;

        __nv_bfloat16 hx = __float2bfloat16(o.x), hy = __float2bfloat16(o.y);
        __nv_bfloat16 hz = __float2bfloat16(o.z), hw = __float2bfloat16(o.w);
        float rx = o.x - __bfloat162float(hx), ry = o.y - __bfloat162float(hy);
        float rz = o.z - __bfloat162float(hz), rw = o.w - __bfloat162float(hw);
        __nv_bfloat162 h01 = __nv_bfloat162(hx, hy), h23 = __nv_bfloat162(hz, hw);
        __nv_bfloat162 l01 = __floats2bfloat162_rn(rx, ry), l23 = __floats2bfloat162_rn(rz, rw);
        uint2 uh, ul;
        uh.x = *reinterpret_cast<uint32_t*>(&h01); uh.y = *reinterpret_cast<uint32_t*>(&h23);
        ul.x = *reinterpret_cast<uint32_t*>(&l01); ul.y = *reinterpret_cast<uint32_t*>(&l23);
        hdst[lane + 32 * i] = uh;
        ldst[lane + 32 * i] = ul;
    }
}

// ---------------- 2. W transpose + hi/lo split ----------------
__global__ void __launch_bounds__(256) prep_w_kernel(const float* __restrict__ Wkv)
{
    __shared__ float s[64][33];
    int n0 = blockIdx.x * 32;
    int k0 = blockIdx.y * 64;
    int tid = threadIdx.x;

#pragma unroll
    for (int it = 0; it < 8; it++) {
        int idx = it * 256 + tid;
        int i = idx >> 5, j = idx & 31;
        s[i][j] = Wkv[(size_t)(k0 + i) * (2 * IND) + n0 + j];
    }
    __syncthreads();

#pragma unroll
    for (int it = 0; it < 4; it++) {
        int idx = it * 256 + tid;
        int j  = idx >> 5;
        int ii = (idx & 31) * 2;
        float v0 = s[ii][j], v1 = s[ii + 1][j];
        __nv_bfloat16 h0 = __float2bfloat16(v0), h1 = __float2bfloat16(v1);
        float r0 = v0 - __bfloat162float(h0), r1 = v1 - __bfloat162float(h1);
        __nv_bfloat162 hp = __nv_bfloat162(h0, h1);
        __nv_bfloat162 lp = __floats2bfloat162_rn(r0, r1);
        size_t off = ((size_t)(n0 + j) * DM + k0 + ii) >> 1;
        reinterpret_cast<uint32_t*>(g_Whi)[off] = *reinterpret_cast<uint32_t*>(&hp);
        reinterpret_cast<uint32_t*>(g_Wlo)[off] = *reinterpret_cast<uint32_t*>(&lp);
    }
}

// ---------------- 3a. q = ln @ Wq, smem-tiled split-K ----------------
// grid (4 ntiles x 128, 4 mtiles x 64, 4 ktiles x 256), 256 threads.
// Per CTA: 64x128 outputs, K slice 256 (8 chunks of 32). Partial -> g_qp.
__global__ void __launch_bounds__(256) q_gemm_tiled(const float* __restrict__ Wq)
{
    __shared__ float As[32][68];
    __shared__ float Ws[32][128];
    int nt = blockIdx.x, mt = blockIdx.y, kt = blockIdx.z;
    int tid = threadIdx.x;
    int rowg = tid >> 4;          // 0..15 -> rows rowg*4
    int colg = tid & 15;          // 0..15 -> cols colg*8

    float acc[4][8];
#pragma unroll
    for (int r = 0; r < 4; r++)
#pragma unroll
        for (int c = 0; c < 8; c++) acc[r][c] = 0.f;

    for (int kc = 0; kc < 256; kc += 32) {
        int kbase = kt * 256 + kc;
        __syncthreads();
        // A chunk: 64 rows x 32 k = 512 float4
#pragma unroll
        for (int i = 0; i < 2; i++) {
            int idx = i * 256 + tid;
            int row = idx >> 3, kq = (idx & 7) * 4;
            float4 a = *reinterpret_cast<const float4*>(
                g_ln + (size_t)(mt * 64 + row) * DM + kbase + kq);
            As[kq + 0][row] = a.x; As[kq + 1][row] = a.y;
            As[kq + 2][row] = a.z; As[kq + 3][row] = a.w;
        }
        // W chunk: 32 rows x 128 cols = 1024 float4
#pragma unroll
        for (int i = 0; i < 4; i++) {
            int idx = i * 256 + tid;
            int wr = idx >> 5, wc = (idx & 31) * 4;
            float4 w = *reinterpret_cast<const float4*>(
                Wq + (size_t)(kbase + wr) * IND + nt * 128 + wc);
            *reinterpret_cast<float4*>(&Ws[wr][wc]) = w;
        }
        __syncthreads();

#pragma unroll
        for (int kk = 0; kk < 32; kk++) {
            float4 av = *reinterpret_cast<const float4*>(&As[kk][rowg * 4]);
            float4 w0 = *reinterpret_cast<const float4*>(&Ws[kk][colg * 8]);
            float4 w1 = *reinterpret_cast<const float4*>(&Ws[kk][colg * 8 + 4]);
            float a4[4] = {av.x, av.y, av.z, av.w};
#pragma unroll
            for (int r = 0; r < 4; r++) {
                acc[r][0] += a4[r] * w0.x; acc[r][1] += a4[r] * w0.y;
                acc[r][2] += a4[r] * w0.z; acc[r][3] += a4[r] * w0.w;
                acc[r][4] += a4[r] * w1.x; acc[r][5] += a4[r] * w1.y;
                acc[r][6] += a4[r] * w1.z; acc[r][7] += a4[r] * w1.w;
            }
        }
    }

    float* dst = g_qp + (size_t)kt * ROWS_L * IND;
#pragma unroll
    for (int r = 0; r < 4; r++) {
        size_t o = (size_t)(mt * 64 + rowg * 4 + r) * IND + nt * 128 + colg * 8;
        *reinterpret_cast<float4*>(dst + o)     = make_float4(acc[r][0], acc[r][1], acc[r][2], acc[r][3]);
        *reinterpret_cast<float4*>(dst + o + 4) = make_float4(acc[r][4], acc[r][5], acc[r][6], acc[r][7]);
    }
}

// q reduce: g_q = sum_{kt<4} g_qp[kt]
__global__ void __launch_bounds__(256) q_reduce_kernel()
{
    int i = blockIdx.x * 256 + threadIdx.x;    // float4 index, 32768 total
    const float4* p = reinterpret_cast<const float4*>(g_qp);
    float4 a = p[i];
    float4 b = p[i + 32768];
    float4 c = p[i + 65536];
    float4 d = p[i + 98304];
    float4 o;
    o.x = (a.x + b.x) + (c.x + d.x);
    o.y = (a.y + b.y) + (c.y + d.y);
    o.z = (a.z + b.z) + (c.z + d.z);
    o.w = (a.w + b.w) + (c.w + d.w);
    reinterpret_cast<float4*>(g_q)[i] = o;
}

// ---------------- 4. KV GEMM (unchanged — at floor) ----------------
#define OFF_AHI 0
#define OFF_ALO 16384
#define OFF_WHI 32768
#define OFF_WLO 49152
#define STAGE_BYTES 65536
#define NSTAGE 3
#define SM_TM   0
#define SM_MB   64
#define SM_DATA 1024
#define SM_TOT  (SM_DATA + NSTAGE * STAGE_BYTES)

__global__ void __launch_bounds__(256) kv_gemm_tc()
{
#if HAS_TCGEN05
    extern __shared__ char smem[];
    uint32_t sb = smem_u32(smem);
    int tid = threadIdx.x, wid = tid >> 5;
    int ntile = blockIdx.x, mtile = blockIdx.y;

    if (wid == 0) { TC_ALLOC(sb + SM_TM, 512); TC_RELINQ(); }
    if (tid == 0) {
#pragma unroll
        for (int st = 0; st < NSTAGE; st++) {
            MBAR_INIT(sb + SM_MB + st * 16, 256);
            MBAR_INIT(sb + SM_MB + st * 16 + 8, 1);
        }
    }
    __syncthreads();
    uint32_t tmem;
    asm volatile("ld.shared.b32 %0, [%1];" : "=r"(tmem) : "r"(sb + SM_TM));

    const char* Ah = (const char*)g_Ahi + (size_t)(mtile * 256) * 2048;
    const char* Al = (const char*)g_Alo + (size_t)(mtile * 256) * 2048;
    const char* Wh = (const char*)g_Whi + (size_t)(ntile * 256) * 2048;
    const char* Wl = (const char*)g_Wlo + (size_t)(ntile * 256) * 2048;

    uint32_t c_src[4], c_dst[4];
#pragma unroll
    for (int it = 0; it < 4; it++) {
        int idx = it * 256 + tid;
        int row = idx >> 2, cb = idx & 3;
        c_src[it] = (uint32_t)(row * 2048 + cb * 16);
        uint32_t bo = (uint32_t)(row * 64 + cb * 16);
        c_dst[it] = bo ^ ((bo >> 3) & 0x30);
    }

#define FILL_STAGE(st, kc) do { \
        uint32_t sbase = sb + SM_DATA + (st) * STAGE_BYTES; \
        uint32_t koff = (uint32_t)(kc) * 64; \
        _Pragma("unroll") \
        for (int it = 0; it < 4; it++) { \
            cp16(sbase + OFF_AHI + c_dst[it], Ah + c_src[it] + koff); \
            cp16(sbase + OFF_ALO + c_dst[it], Al + c_src[it] + koff); \
            cp16(sbase + OFF_WHI + c_dst[it], Wh + c_src[it] + koff); \
            cp16(sbase + OFF_WLO + c_dst[it], Wl + c_src[it] + koff); \
        } \
        CP_MBAR_ARRIVE(sb + SM_MB + (st) * 16); \
    } while (0)

    FILL_STAGE(0, 0);
    FILL_STAGE(1, 1);
    FILL_STAGE(2, 2);

    int fc[NSTAGE] = {0, 0, 0};
    int ec[NSTAGE] = {0, 0, 0};

    for (int kc = 0; kc < 32; kc++) {
        int st = kc - (kc / 3) * 3;

        if (wid == 0 && elect_one()) {
            MBAR_WAIT(sb + SM_MB + st * 16, (uint32_t)(fc[st] & 1));
            fc[st]++;
            FENCE_ASYNC();
            uint32_t sbase = sb + SM_DATA + st * STAGE_BYTES;
            uint64_t ahd = make_desc64(sbase + OFF_AHI);
            uint64_t ald = make_desc64(sbase + OFF_ALO);
            uint64_t whd = make_desc64(sbase + OFF_WHI);
            uint64_t wld = make_desc64(sbase + OFF_WLO);
#pragma unroll
            for (int sub = 0; sub < 2; sub++) {
                uint32_t dtm = tmem + sub * 256;
                uint64_t aoff = (uint64_t)(sub * 512);
#pragma unroll
                for (int s = 0; s < 2; s++) {
                    uint32_t en = !(kc == 0 && s == 0);
                    mma_f16_ss(dtm, ahd + aoff + s * 2, whd + s * 2, KV_IDESC, en);
                }
#pragma unroll
                for (int s = 0; s < 2; s++)
                    mma_f16_ss(dtm, ahd + aoff + s * 2, wld + s * 2, KV_IDESC, 1);
#pragma unroll
                for (int s = 0; s < 2; s++)
                    mma_f16_ss(dtm, ald + aoff + s * 2, whd + s * 2, KV_IDESC, 1);
            }
            TC_COMMIT(sb + SM_MB + st * 16 + 8);
        }

        if (kc >= 1 && kc + 2 <= 31) {
            int stp = (kc + 2) - ((kc + 2) / 3) * 3;
            MBAR_WAIT(sb + SM_MB + stp * 16 + 8, (uint32_t)(ec[stp] & 1));
            ec[stp]++;
            FILL_STAGE(stp, kc + 2);
        }
    }

#pragma unroll
    for (int st = 0; st < NSTAGE; st++) {
        MBAR_WAIT(sb + SM_MB + st * 16 + 8, (uint32_t)(ec[st] & 1));
        ec[st]++;
    }
    TC_FENCE_AFTER();

    {
        int lane = tid & 31;
        int half = wid >> 2;
        int wiw  = wid & 3;
        uint32_t tbase = tmem + half * 256;
        size_t rowg = (size_t)(mtile * 256 + half * 128 + wiw * 32 + lane);
        float* dst = g_kv + rowg * (2 * IND) + ntile * 256;
#pragma unroll
        for (int cb = 0; cb < 8; cb++) {
            uint32_t r[32];
            LDTM_X32(r, tbase + cb * 32);
            TC_WAIT_LD();
#pragma unroll
            for (int j = 0; j < 32; j += 4) {
                uint4 v;
                v.x = r[j]; v.y = r[j + 1]; v.z = r[j + 2]; v.w = r[j + 3];
                *reinterpret_cast<uint4*>(dst + cb * 32 + j) = v;
            }
        }
    }
    __syncthreads();
    if (wid == 0) TC_DEALLOC(tmem, 512);
#undef FILL_STAGE
#else
    int tid = threadIdx.x;
    int ntile = blockIdx.x, mtile = blockIdx.y;
    for (int i = tid; i < 256 * 256; i += 256) {
        int r = i >> 8, cc = i & 255;
        size_t row = (size_t)mtile * 256 + r;
        size_t col = (size_t)ntile * 256 + cc;
        float acc = 0.f;
        for (int k = 0; k < DM; k++) {
            float a = __bfloat162float(g_Ahi[row * DM + k]) + __bfloat162float(g_Alo[row * DM + k]);
            float w = __bfloat162float(g_Whi[col * DM + k]) + __bfloat162float(g_Wlo[col * DM + k]);
            acc += a * w;
        }
        g_kv[row * (2 * IND) + col] = acc;
    }
#endif
}

// ---------------- 5. split-KV flash attention (R13/R15 form) ----------------
#define AQ_QS 0
#define AQ_KS 4096
#define AQ_VS 12800
#define AQ_PS 20992
#define AQ_TOT_F 25344
#define KS_STRIDE 68
#define PS_STRIDE 68

__global__ void __launch_bounds__(512) attn_kernel()
{
    extern __shared__ float sm[];
    float* QS = sm + AQ_QS;
    float* KS = sm + AQ_KS;
    float* VS = sm + AQ_VS;
    float* PS = sm + AQ_PS;
    uint32_t ks_u = smem_u32(KS);
    uint32_t vs_u = smem_u32(VS);

    int bh = blockIdx.y;
    int b = bh >> 3, h = bh & 7;
    int tid = threadIdx.x, w = tid >> 5, lane = tid & 31;

#pragma unroll
    for (int j = 0; j < 2; j++) {
        int idx = tid + j * 512;
        int row = idx >> 4, d = (idx & 15) * 4;
        float4 q = *reinterpret_cast<const float4*>(
            g_q + (size_t)(b * 64 + row) * IND + h * 64 + d);
        q.x *= 8.f; q.y *= 8.f; q.z *= 8.f; q.w *= 8.f;
        *reinterpret_cast<float4*>(QS + row * 64 + d) = q;
    }

    int s0beg = blockIdx.x * CHUNK_KEYS;
    int s0end = min(S_TOT, s0beg + CHUNK_KEYS);
    int ntiles = (s0end - s0beg) >> 6;

    int ckey = tid >> 3, cpart = tid & 7;
    const char* kv_base = (const char*)(g_kv + (size_t)(b * S_TOT) * (2 * IND)) + h * 256;

#define ISSUE_TILE(t, buf) do { \
        const char* srcr = kv_base + (size_t)(s0beg + (t) * 64 + ckey) * 4096; \
        cp16(ks_u + ((buf) * 4352 + ckey * KS_STRIDE + cpart * 4) * 4,        srcr + cpart * 16); \
        cp16(ks_u + ((buf) * 4352 + ckey * KS_STRIDE + (cpart + 8) * 4) * 4,  srcr + (cpart + 8) * 16); \
        cp16(vs_u + ((buf) * 4096 + ckey * 64 + cpart * 4) * 4,               srcr + 2048 + cpart * 16); \
        cp16(vs_u + ((buf) * 4096 + ckey * 64 + (cpart + 8) * 4) * 4,         srcr + 2048 + (cpart + 8) * 16); \
        CP_COMMIT(); \
    } while (0)

    ISSUE_TILE(0, 0);

    int r0 = w * 4;
    float m[4], l[4];
    float2 o[4];
#pragma unroll
    for (int r = 0; r < 4; r++) { m[r] = -3.0e38f; l[r] = 0.f; o[r] = make_float2(0.f, 0.f); }
    int dlo = lane * 2;

    for (int t = 0; t < ntiles; t++) {
        int buf = t & 1;
        if (t + 1 < ntiles) { ISSUE_TILE(t + 1, (t + 1) & 1); CP_WAIT(1); }
        else                { CP_WAIT(0); }
        __syncthreads();

        float s0[4] = {0.f, 0.f, 0.f, 0.f};
        float s1[4] = {0.f, 0.f, 0.f, 0.f};
        const float* kr0 = KS + buf * 4352 + lane * KS_STRIDE;
        const float* kr1 = kr0 + 32 * KS_STRIDE;
#pragma unroll
        for (int db = 0; db < 16; db++) {
            float4 k0 = *reinterpret_cast<const float4*>(kr0 + db * 4);
            float4 k1 = *reinterpret_cast<const float4*>(kr1 + db * 4);
#pragma unroll
            for (int r = 0; r < 4; r++) {
                float4 qf = *reinterpret_cast<const float4*>(QS + (r0 + r) * 64 + db * 4);
                s0[r] += qf.x * k0.x + qf.y * k0.y + qf.z * k0.z + qf.w * k0.w;
                s1[r] += qf.x * k1.x + qf.y * k1.y + qf.z * k1.z + qf.w * k1.w;
            }
        }

        float alpha[4];
#pragma unroll
        for (int r = 0; r < 4; r++) {
            float tm = warpMax(fmaxf(s0[r], s1[r]));
            float mn = fmaxf(m[r], tm);
            float p0 = __expf(s0[r] - mn);
            float p1 = __expf(s1[r] - mn);
            alpha[r] = __expf(m[r] - mn);
            float psum = warpSum(p0 + p1);
            l[r] = l[r] * alpha[r] + psum;
            m[r] = mn;
            PS[(r0 + r) * PS_STRIDE + lane]      = p0;
            PS[(r0 + r) * PS_STRIDE + 32 + lane] = p1;
        }
        __syncwarp();

        const float* vb = VS + buf * 4096;
#pragma unroll
        for (int r = 0; r < 4; r++) { o[r].x *= alpha[r]; o[r].y *= alpha[r]; }
#pragma unroll
        for (int k4 = 0; k4 < 16; k4++) {
            float2 v0 = *reinterpret_cast<const float2*>(vb + (k4 * 4 + 0) * 64 + dlo);
            float2 v1 = *reinterpret_cast<const float2*>(vb + (k4 * 4 + 1) * 64 + dlo);
            float2 v2 = *reinterpret_cast<const float2*>(vb + (k4 * 4 + 2) * 64 + dlo);
            float2 v3 = *reinterpret_cast<const float2*>(vb + (k4 * 4 + 3) * 64 + dlo);
#pragma unroll
            for (int r = 0; r < 4; r++) {
                float4 pb = *reinterpret_cast<const float4*>(PS + (r0 + r) * PS_STRIDE + k4 * 4);
                o[r].x += pb.x * v0.x + pb.y * v1.x + pb.z * v2.x + pb.w * v3.x;
                o[r].y += pb.x * v0.y + pb.y * v1.y + pb.z * v2.y + pb.w * v3.y;
            }
        }
        __syncthreads();
    }

    int c = bh * NCHUNK + blockIdx.x;
#pragma unroll
    for (int r = 0; r < 4; r++) {
        int row = r0 + r;
        *reinterpret_cast<float2*>(g_po + ((size_t)c * 64 + row) * 64 + dlo) = o[r];
        if (lane == 0) { g_pm[c * 64 + row] = m[r]; g_pl[c * 64 + row] = l[r]; }
    }
#undef ISSUE_TILE
}

// ---------------- 6. merge split-KV partials ----------------
__global__ void __launch_bounds__(256) merge_kernel()
{
    int bh = blockIdx.x;
    int b = bh >> 3, h = bh & 7;
    int tid = threadIdx.x;
    int row = tid >> 2;
    int dp  = (tid & 3) * 16;

    float mx = -3.0e38f;
    for (int c = 0; c < NCHUNK; c++)
        mx = fmaxf(mx, g_pm[(bh * NCHUNK + c) * 64 + row]);

    float Ls = 0.f;
    float acc[16];
#pragma unroll
    for (int j = 0; j < 16; j++) acc[j] = 0.f;

    for (int c = 0; c < NCHUNK; c++) {
        int idx = (bh * NCHUNK + c) * 64 + row;
        float wgt = __expf(g_pm[idx] - mx);
        Ls += wgt * g_pl[idx];
        const float* po = g_po + (size_t)idx * 64 + dp;
#pragma unroll
        for (int j = 0; j < 16; j++) acc[j] += wgt * po[j];
    }
    float inv = 1.0f / Ls;
    float* dst = g_ao + (size_t)(b * 64 + row) * IND + h * 64 + dp;
#pragma unroll
    for (int j = 0; j < 16; j++) dst[j] = acc[j] * inv;
}

// ---------------- 7a. out = attn_out @ Wout, smem-tiled split-K ----------------
// grid (8 ntiles x 128, 4 mtiles x 64, 2 ktiles x 256), 256 threads. Partial -> g_outp.
__global__ void __launch_bounds__(256) out_gemm_tiled(const float* __restrict__ Wout)
{
    __shared__ float As[32][68];
    __shared__ float Ws[32][128];
    int nt = blockIdx.x, mt = blockIdx.y, kt = blockIdx.z;
    int tid = threadIdx.x;
    int rowg = tid >> 4;
    int colg = tid & 15;

    float acc[4][8];
#pragma unroll
    for (int r = 0; r < 4; r++)
#pragma unroll
        for (int c = 0; c < 8; c++) acc[r][c] = 0.f;

    for (int kc = 0; kc < 256; kc += 32) {
        int kbase = kt * 256 + kc;
        __syncthreads();
#pragma unroll
        for (int i = 0; i < 2; i++) {
            int idx = i * 256 + tid;
            int row = idx >> 3, kq = (idx & 7) * 4;
            float4 a = *reinterpret_cast<const float4*>(
                g_ao + (size_t)(mt * 64 + row) * IND + kbase + kq);
            As[kq + 0][row] = a.x; As[kq + 1][row] = a.y;
            As[kq + 2][row] = a.z; As[kq + 3][row] = a.w;
        }
#pragma unroll
        for (int i = 0; i < 4; i++) {
            int idx = i * 256 + tid;
            int wr = idx >> 5, wc = (idx & 31) * 4;
            float4 w = *reinterpret_cast<const float4*>(
                Wout + (size_t)(kbase + wr) * DM + nt * 128 + wc);
            *reinterpret_cast<float4*>(&Ws[wr][wc]) = w;
        }
        __syncthreads();

#pragma unroll
        for (int kk = 0; kk < 32; kk++) {
            float4 av = *reinterpret_cast<const float4*>(&As[kk][rowg * 4]);
            float4 w0 = *reinterpret_cast<const float4*>(&Ws[kk][colg * 8]);
            float4 w1 = *reinterpret_cast<const float4*>(&Ws[kk][colg * 8 + 4]);
            float a4[4] = {av.x, av.y, av.z, av.w};
#pragma unroll
            for (int r = 0; r < 4; r++) {
                acc[r][0] += a4[r] * w0.x; acc[r][1] += a4[r] * w0.y;
                acc[r][2] += a4[r] * w0.z; acc[r][3] += a4[r] * w0.w;
                acc[r][4] += a4[r] * w1.x; acc[r][5] += a4[r] * w1.y;
                acc[r][6] += a4[r] * w1.z; acc[r][7] += a4[r] * w1.w;
            }
        }
    }

    float* dst = g_outp + (size_t)kt * ROWS_L * DM;
#pragma unroll
    for (int r = 0; r < 4; r++) {
        size_t o = (size_t)(mt * 64 + rowg * 4 + r) * DM + nt * 128 + colg * 8;
        *reinterpret_cast<float4*>(dst + o)     = make_float4(acc[r][0], acc[r][1], acc[r][2], acc[r][3]);
        *reinterpret_cast<float4*>(dst + o + 4) = make_float4(acc[r][4], acc[r][5], acc[r][6], acc[r][7]);
    }
}

// out reduce: out = g_outp[0] + g_outp[1]
__global__ void __launch_bounds__(256) out_reduce_kernel(float* __restrict__ out)
{
    int i = blockIdx.x * 256 + threadIdx.x;    // float4 index, 65536 total
    const float4* p = reinterpret_cast<const float4*>(g_outp);
    float4 a = p[i];
    float4 b = p[i + 65536];
    float4 o;
    o.x = a.x + b.x; o.y = a.y + b.y; o.z = a.z + b.z; o.w = a.w + b.w;
    reinterpret_cast<float4*>(out)[i] = o;
}

// ---------------- launch ----------------
extern "C" void kernel_launch(void* const* d_in, const int* in_sizes, int n_in,
                              void* d_out, int out_size)
{
    const float* x    = (const float*)d_in[0];
    const float* lat  = (const float*)d_in[1];
    const float* Wq   = (const float*)d_in[2];
    const float* Wkv  = (const float*)d_in[3];
    const float* Wout = (const float*)d_in[4];
    const float* gm   = (const float*)d_in[5];
    const float* bm   = (const float*)d_in[6];
    const float* gl   = (const float*)d_in[7];
    const float* bl   = (const float*)d_in[8];
    float* out = (float*)d_out;

    cudaFuncSetAttribute(kv_gemm_tc, cudaFuncAttributeMaxDynamicSharedMemorySize, SM_TOT);
    cudaFuncSetAttribute(attn_kernel, cudaFuncAttributeMaxDynamicSharedMemorySize, AQ_TOT_F * 4);

    prep_a_kernel<<<ROWS_KV / 8, 256>>>(x, lat, gm, bm, gl, bl);
    prep_w_kernel<<<dim3(32, 16), 256>>>(Wkv);
    q_gemm_tiled<<<dim3(4, 4, 4), 256>>>(Wq);
    q_reduce_kernel<<<128, 256>>>();
    kv_gemm_tc<<<dim3(4, 129), 256, SM_TOT>>>();
    attn_kernel<<<dim3(NCHUNK, 32), 512, AQ_TOT_F * 4>>>();
    merge_kernel<<<32, 256>>>();
    out_gemm_tiled<<<dim3(8, 4, 2), 256>>>(Wout);
    out_reduce_kernel<<<256, 256>>>(out);
}